// round 16
// baseline (speedup 1.0000x reference)
#include <cuda_runtime.h>
#include <math.h>

#define NFR 64
#define NPX 65536          // 256*256
#define NTOT (NFR*NPX)     // 4194304 = 2^22
#define M22  0x3FFFFF      // NTOT-1 safety mask
#define SIGMA 0.35355339059327373f
#define TAU   0.35355339059327373f
#define INV1PS (1.0f/(1.0f+SIGMA))
#define ELD 65             // A smem leading dim (padded)
#define NSWEEP 5
#define GRAMB 128          // gram partial blocks

#define IDX(i) ((i) & M22)

// ---------------- device globals (scratch) ----------------
__device__ float2 g_D[NTOT];
__device__ float2 g_T[NTOT];
__device__ float2 g_y1[NTOT];
__device__ float2 g_y2[NTOT];
__device__ float2 g_x1[NTOT];
__device__ float2 g_x2[NTOT];
__device__ float2 g_u1[NTOT];
__device__ float2 g_u2[NTOT];
__device__ float2 g_A1[NTOT];
__device__ double g_part[256];
__device__ double g_norm2;
__device__ float2 g_Gp[GRAMB][4096];
__device__ float2 g_Gf[4096];
__device__ float2 g_W[4096];
__device__ float2 g_tw[128];

// ---------------- helpers ----------------
__device__ __forceinline__ float2 cadd(float2 a, float2 b){ return make_float2(a.x+b.x, a.y+b.y); }
__device__ __forceinline__ float2 csub(float2 a, float2 b){ return make_float2(a.x-b.x, a.y-b.y); }
__device__ __forceinline__ float2 cmulf(float2 a, float2 b){ return make_float2(a.x*b.x-a.y*b.y, a.x*b.y+a.y*b.x); }
// conj(s)*a
__device__ __forceinline__ float2 cjmul(float2 s, float2 a){ return make_float2(s.x*a.x+s.y*a.y, s.x*a.y-s.y*a.x); }
__device__ __forceinline__ float2 cscale(float2 a, float c){ return make_float2(a.x*c, a.y*c); }

// 256-pt radix-2 DIT FFT on shared memory, one warp per line.
__device__ __forceinline__ void fft256_sm(float2* s, int stride, int lane, int inv) {
    #pragma unroll
    for (int j = 0; j < 8; j++) {
        int i = lane + (j<<5);
        int r = __brev((unsigned)i) >> 24;
        if (r > i) { float2 a = s[i*stride]; s[i*stride] = s[r*stride]; s[r*stride] = a; }
    }
    __syncwarp();
    #pragma unroll
    for (int st = 0; st < 8; st++) {
        int half = 1 << st;
        #pragma unroll
        for (int j = 0; j < 4; j++) {
            int b  = lane + (j<<5);
            int k  = b & (half-1);
            int i0 = ((b >> st) << (st+1)) + k;
            float2 w = g_tw[(k << (7-st)) & 127];
            if (inv) w.y = -w.y;
            float2 u = s[i0*stride];
            float2 v = s[(i0+half)*stride];
            float2 t = cmulf(w, v);
            s[i0*stride]        = cadd(u, t);
            s[(i0+half)*stride] = csub(u, t);
        }
        __syncwarp();
    }
}

// ---------------- init ----------------
__global__ __launch_bounds__(128) void k_init() {
    int t = threadIdx.x & 127;
    double a = -2.0 * 3.14159265358979323846 * (double)t / 256.0;
    g_tw[t] = make_float2((float)cos(a), (float)sin(a));
}

__global__ __launch_bounds__(256) void k_sumsq(const float* __restrict__ dr, const float* __restrict__ di, int cap) {
    double acc = 0.0;
    for (int i = blockIdx.x*blockDim.x + threadIdx.x; i < cap; i += gridDim.x*blockDim.x) {
        float a = dr[i], b = di[i];
        acc += (double)a*(double)a + (double)b*(double)b;
    }
    __shared__ double ws[256];
    ws[threadIdx.x] = acc;
    __syncthreads();
    for (int o = 128; o; o >>= 1) {
        if (threadIdx.x < o) ws[threadIdx.x] += ws[threadIdx.x + o];
        __syncthreads();
    }
    if (threadIdx.x == 0) g_part[blockIdx.x & 255] = ws[0];
}

__global__ __launch_bounds__(256) void k_normred() {
    __shared__ double ws[256];
    ws[threadIdx.x] = g_part[threadIdx.x & 255];
    __syncthreads();
    for (int o = 128; o; o >>= 1) {
        if (threadIdx.x < o) ws[threadIdx.x] += ws[threadIdx.x + o];
        __syncthreads();
    }
    if (threadIdx.x == 0) g_norm2 = ws[0];
}

__global__ __launch_bounds__(256) void k_buildD(const float* __restrict__ dr, const float* __restrict__ di, int cap) {
    float inv = (float)(1.0 / sqrt(g_norm2));
    for (int i = blockIdx.x*blockDim.x + threadIdx.x; i < NTOT; i += gridDim.x*blockDim.x) {
        float a = (i < cap) ? dr[i] : 0.f;
        float b = (i < cap) ? di[i] : 0.f;
        g_D[IDX(i)]  = make_float2(a*inv, b*inv);
        g_y1[IDX(i)] = make_float2(0.f, 0.f);
        g_y2[IDX(i)] = make_float2(0.f, 0.f);
    }
}

// ---------------- FFT row pass ----------------
__global__ __launch_bounds__(256) void k_fft_row(int mode, int inv, const float* __restrict__ lamSp, int lamIdx) {
    __shared__ float2 sm[8*256];
    int warp = threadIdx.x >> 5, lane = threadIdx.x & 31;
    int line = (blockIdx.x << 3) + warp;
    int base = line << 8;
    int f = line >> 8;
    float2* s = sm + (warp << 8);
    if (mode == 1) {
        float lamS = lamSp ? fmaxf(lamSp[lamIdx], 0.f) : 0.01f;
        float l2 = lamS*lamS;
        #pragma unroll
        for (int j = 0; j < 8; j++) {
            int i = lane + (j<<5);
            float2 u1v = g_u1[IDX(base+i)];
            float2 u2v = g_u2[IDX(base+i)];
            s[i] = cadd(u1v, u2v);
            float2 a = g_y2[IDX(base+i)];
            if (f < NFR-1) {
                float2 un = g_u2[IDX(base+i+NPX)];
                a.x += SIGMA*(un.x - u2v.x);
                a.y += SIGMA*(un.y - u2v.y);
            }
            float m2 = a.x*a.x + a.y*a.y;
            if (m2 > l2) {
                float sc = lamS * rsqrtf(m2);
                a.x *= sc; a.y *= sc;
            }
            g_y2[IDX(base+i)] = a;
        }
    } else {
        #pragma unroll
        for (int j = 0; j < 8; j++) { int i = lane + (j<<5); s[i] = g_D[IDX(base+i)]; }
    }
    __syncwarp();
    fft256_sm(s, 1, lane, inv);
    #pragma unroll
    for (int j = 0; j < 8; j++) {
        int i = lane + (j<<5);
        float2 v = s[i];
        g_T[IDX(base+i)] = make_float2(v.x*0.0625f, v.y*0.0625f);
    }
}

// startpoint: inverse col pass; broadcast result into x1,x2,u1,u2
__global__ __launch_bounds__(256) void k_col_start() {
    __shared__ float2 sm[256*9];
    int f = blockIdx.x >> 5, x0 = (blockIdx.x & 31) << 3;
    int fb = f << 16;
    int lx = threadIdx.x & 7, ly = threadIdx.x >> 3;
    #pragma unroll
    for (int i2 = 0; i2 < 8; i2++) {
        int y = (i2<<5) + ly;
        sm[y*9 + lx] = g_T[IDX(fb + (y<<8) + x0 + lx)];
    }
    __syncthreads();
    int warp = threadIdx.x >> 5, lane = threadIdx.x & 31;
    fft256_sm(sm + warp, 9, lane, 1);
    __syncthreads();
    #pragma unroll
    for (int i2 = 0; i2 < 8; i2++) {
        int y = (i2<<5) + ly;
        int idx = IDX(fb + (y<<8) + x0 + lx);
        float2 v = sm[y*9 + lx];
        v = make_float2(v.x*0.0625f, v.y*0.0625f);
        g_x1[idx] = v; g_x2[idx] = v; g_u1[idx] = v; g_u2[idx] = v;
    }
}

// FUSED column pass: forward col FFT -> y1 dual update -> inverse col FFT.
__global__ __launch_bounds__(256) void k_col_fused() {
    __shared__ float2 sm[256*9];
    int f = blockIdx.x >> 5, x0 = (blockIdx.x & 31) << 3;
    int fb = f << 16;
    int lx = threadIdx.x & 7, ly = threadIdx.x >> 3;
    #pragma unroll
    for (int i2 = 0; i2 < 8; i2++) {
        int y = (i2<<5) + ly;
        sm[y*9 + lx] = g_T[IDX(fb + (y<<8) + x0 + lx)];
    }
    __syncthreads();
    int warp = threadIdx.x >> 5, lane = threadIdx.x & 31;
    fft256_sm(sm + warp, 9, lane, 0);     // forward column FFT
    __syncthreads();
    #pragma unroll
    for (int i2 = 0; i2 < 8; i2++) {
        int y = (i2<<5) + ly;
        int idx = IDX(fb + (y<<8) + x0 + lx);
        float2 v = sm[y*9 + lx];
        v.x *= 0.0625f; v.y *= 0.0625f;   // true Ku1
        float2 d = g_D[idx];
        float2 yv = g_y1[idx];
        yv.x = (yv.x + SIGMA*(v.x - d.x)) * INV1PS;
        yv.y = (yv.y + SIGMA*(v.y - d.y)) * INV1PS;
        g_y1[idx] = yv;
        sm[y*9 + lx] = yv;
    }
    __syncthreads();
    fft256_sm(sm + warp, 9, lane, 1);     // inverse column FFT of y1'
    __syncthreads();
    #pragma unroll
    for (int i2 = 0; i2 < 8; i2++) {
        int y = (i2<<5) + ly;
        float2 v = sm[y*9 + lx];
        g_T[IDX(fb + (y<<8) + x0 + lx)] = make_float2(v.x*0.0625f, v.y*0.0625f);
    }
}

// inverse ROW pass of g_T -> Kadjy1; fused argg1 and x2/u2 updates
__global__ __launch_bounds__(256) void k_row_kadj() {
    __shared__ float2 smr[8*256];
    int warp = threadIdx.x >> 5, lane = threadIdx.x & 31;
    int line = (blockIdx.x << 3) + warp;
    int base = line << 8;
    int f = line >> 8;
    float2* s = smr + (warp << 8);
    #pragma unroll
    for (int j = 0; j < 8; j++) { int i = lane + (j<<5); s[i] = g_T[IDX(base+i)]; }
    __syncwarp();
    fft256_sm(s, 1, lane, 1);
    #pragma unroll
    for (int j = 0; j < 8; j++) {
        int i = lane + (j<<5);
        int idx = IDX(base + i);
        float2 v = s[i];
        v.x *= 0.0625f; v.y *= 0.0625f;   // Kadjy1
        float2 x = g_x1[idx];
        g_A1[idx] = make_float2(x.x - TAU*v.x, x.y - TAU*v.y);
        float2 kadj;
        if (f == 0) {
            float2 yc = g_y2[idx];
            kadj = make_float2(v.x - yc.x, v.y - yc.y);
        } else if (f == NFR-1) {
            float2 ym = g_y2[IDX(idx - NPX)];
            kadj = make_float2(v.x + ym.x, v.y + ym.y);
        } else {
            float2 yc = g_y2[idx];
            float2 ym = g_y2[IDX(idx - NPX)];
            kadj = make_float2(v.x - (yc.x - ym.x), v.y - (yc.y - ym.y));
        }
        float2 xo = g_x2[idx];
        float2 xn = make_float2(xo.x - TAU*kadj.x, xo.y - TAU*kadj.y);
        g_x2[idx] = xn;
        g_u2[idx] = make_float2(2.f*xn.x - xo.x, 2.f*xn.y - xo.y);
    }
}

// Gram partials with 4x4 register blocking.
__global__ __launch_bounds__(256) void k_gram() {
    __shared__ float2 tile[64][33];
    int tid = threadIdx.x;
    int tx = tid & 15, ty = tid >> 4;
    float2 acc[4][4];
    #pragma unroll
    for (int i = 0; i < 4; i++)
        #pragma unroll
        for (int j = 0; j < 4; j++) acc[i][j] = make_float2(0.f, 0.f);
    int p0 = blockIdx.x * (NPX / GRAMB);
    for (int pt = 0; pt < NPX/GRAMB; pt += 32) {
        for (int l = tid; l < 2048; l += 256) {
            int gg = l >> 5, pp = l & 31;
            tile[gg][pp] = g_A1[IDX(gg*NPX + p0 + pt + pp)];
        }
        __syncthreads();
        for (int p = 0; p < 32; p++) {
            float2 ag[4], bh[4];
            #pragma unroll
            for (int i = 0; i < 4; i++) ag[i] = tile[ty + 16*i][p];
            #pragma unroll
            for (int j = 0; j < 4; j++) bh[j] = tile[tx + 16*j][p];
            #pragma unroll
            for (int i = 0; i < 4; i++)
                #pragma unroll
                for (int j = 0; j < 4; j++) {
                    float2 a = ag[i], b = bh[j];
                    acc[i][j].x += a.x*b.x + a.y*b.y;   // conj(a)*b
                    acc[i][j].y += a.x*b.y - a.y*b.x;
                }
        }
        __syncthreads();
    }
    #pragma unroll
    for (int i = 0; i < 4; i++)
        #pragma unroll
        for (int j = 0; j < 4; j++)
            g_Gp[blockIdx.x & (GRAMB-1)][((ty+16*i)*64 + tx+16*j) & 4095] = acc[i][j];
}

__global__ __launch_bounds__(256) void k_gramred() {
    int idx = (blockIdx.x*blockDim.x + threadIdx.x) & 4095;
    double sx = 0.0, sy = 0.0;
    for (int b = 0; b < GRAMB; b++) {
        float2 v = g_Gp[b][idx];
        sx += (double)v.x; sy += (double)v.y;
    }
    g_Gf[idx] = make_float2((float)sx, (float)sy);
}

// rotation computation for pair k of round rnd (reads A only)
__device__ __forceinline__ void rot_compute(const float2* A, const ushort2* pq,
                                            int rnd, int k, float* csr, float2* ssr) {
    ushort2 e = pq[rnd*32 + k];
    int p = e.x, q = e.y;
    float app = A[p*ELD+p].x, aqq = A[q*ELD+q].x;
    float2 apq = A[p*ELD+q];
    float ab = sqrtf(apq.x*apq.x + apq.y*apq.y);
    float c = 1.f; float2 s = make_float2(0.f, 0.f);
    if (ab > 1e-30f) {
        float tt = (aqq - app) / (2.f*ab);
        float t  = 1.f / (fabsf(tt) + sqrtf(1.f + tt*tt));
        if (tt < 0.f) t = -t;
        c = rsqrtf(1.f + t*t);
        float sg = t * c;
        s = make_float2(apq.x/ab*sg, apq.y/ab*sg);
    }
    csr[k] = c; ssr[k] = s;
}

// V column-pair rotation for item u (k = pair, ch = row chunk), float4 path
__device__ __forceinline__ void vt_update(float2* Vt, const ushort2* pq, int rnd, int u,
                                          const float* csr, const float2* ssr) {
    int k = u >> 5, ch = u & 31;
    ushort2 e = pq[rnd*32 + k];
    int p = e.x, q = e.y;
    float c = csr[k]; float2 s = ssr[k];
    int r2 = ch << 1;
    float4* vp4 = reinterpret_cast<float4*>(&Vt[p*64 + r2]);
    float4* vq4 = reinterpret_cast<float4*>(&Vt[q*64 + r2]);
    float4 vp = *vp4, vq = *vq4;
    float2 vp0 = make_float2(vp.x, vp.y), vp1 = make_float2(vp.z, vp.w);
    float2 vq0 = make_float2(vq.x, vq.y), vq1 = make_float2(vq.z, vq.w);
    float2 np0 = csub(cscale(vp0, c), cjmul(s, vq0));
    float2 nq0 = cadd(cmulf(s, vp0), cscale(vq0, c));
    float2 np1 = csub(cscale(vp1, c), cjmul(s, vq1));
    float2 nq1 = cadd(cmulf(s, vp1), cscale(vq1, c));
    *vp4 = make_float4(np0.x, np0.y, np1.x, np1.y);
    *vq4 = make_float4(nq0.x, nq0.y, nq1.x, nq1.y);
}

// ---- 64x64 Hermitian eigensolver: Hermitian-symmetric pipelined Jacobi ----
// A update computes ONLY upper-triangle 2x2 blocks (kr<=kc, 528 of 1024) and
// mirror-writes conjugates; lower-triangle regions are never read (race-free).
// Freed threads absorb half the V-update in phase1; phase2 = rot(r+1) || rest of V.
__global__ __launch_bounds__(1024) void k_eig(const float* __restrict__ lamLp, int lamIdx) {
    extern __shared__ float2 es[];
    float2*  A  = es;                        // 64*ELD
    float2*  Vt = es + 64*ELD;               // 4096: Vt[i*64+r] = V[r][i]
    ushort2* pq = (ushort2*)(es + 64*ELD + 4096);  // 63*32
    uchar2*  tri = (uchar2*)(pq + 63*32);          // 528 (kr<=kc)
    __shared__ float  csr2[2][32];
    __shared__ float2 ssr2[2][32];
    __shared__ float  rr[64];
    int tid = threadIdx.x;   // 1024 threads

    for (int l = tid; l < 4096; l += 1024) {
        int r = l >> 6, c = l & 63;
        A[r*ELD + c] = g_Gf[l & 4095];
        Vt[l & 4095] = (r == c) ? make_float2(1.f, 0.f) : make_float2(0.f, 0.f);
    }
    for (int l = tid; l < 63*32; l += 1024) {
        int rnd = l >> 5, k = l & 31;
        int p, q;
        if (k == 0) { p = 63; q = rnd; }
        else { p = (rnd + k) % 63; q = (rnd - k + 63) % 63; }
        pq[l] = make_ushort2((unsigned short)p, (unsigned short)q);
    }
    {   // upper-triangle block table: linear index for (kr<=kc)
        int kr = tid >> 5, kc = tid & 31;
        if (kr <= kc) {
            int idx = kr*32 - (kr*(kr-1))/2 + (kc - kr);
            tri[idx] = make_uchar2((unsigned char)kr, (unsigned char)kc);
        }
    }
    __syncthreads();

    if (tid < 32) rot_compute(A, pq, 0, tid, csr2[0], ssr2[0]);
    __syncthreads();

    const int R = NSWEEP*63;
    int rnd = 0;
    for (int r = 0; r < R; r++) {
        int cur = r & 1, nxt = cur ^ 1;
        int nrnd = (rnd + 1 == 63) ? 0 : rnd + 1;
        // phase1: threads 0..527 -> upper-tri A blocks (+mirror); 528..1023 -> V items 0..495
        if (tid < 528) {
            uchar2 t = tri[tid];
            int kr = t.x, kc = t.y;
            ushort2 er = pq[rnd*32 + kr], ec = pq[rnd*32 + kc];
            int p_r = er.x, q_r = er.y, p_c = ec.x, q_c = ec.y;
            float cc = csr2[cur][kc]; float2 sc = ssr2[cur][kc];
            float cr = csr2[cur][kr]; float2 sr = ssr2[cur][kr];
            float2 app = A[p_r*ELD+p_c], apq = A[p_r*ELD+q_c];
            float2 aqp = A[q_r*ELD+p_c], aqq = A[q_r*ELD+q_c];
            float2 bpp = csub(cscale(app, cc), cjmul(sc, apq));
            float2 bpq = cadd(cmulf(sc, app), cscale(apq, cc));
            float2 bqp = csub(cscale(aqp, cc), cjmul(sc, aqq));
            float2 bqq = cadd(cmulf(sc, aqp), cscale(aqq, cc));
            float2 npp = csub(cscale(bpp, cr), cmulf(sr, bqp));
            float2 npq = csub(cscale(bpq, cr), cmulf(sr, bqq));
            float2 nqp = cadd(cjmul(sr, bpp), cscale(bqp, cr));
            float2 nqq = cadd(cjmul(sr, bpq), cscale(bqq, cr));
            A[p_r*ELD+p_c] = npp; A[p_r*ELD+q_c] = npq;
            A[q_r*ELD+p_c] = nqp; A[q_r*ELD+q_c] = nqq;
            if (kr != kc) {   // Hermitian mirror into the transpose region
                A[p_c*ELD+p_r] = make_float2(npp.x, -npp.y);
                A[q_c*ELD+p_r] = make_float2(npq.x, -npq.y);
                A[p_c*ELD+q_r] = make_float2(nqp.x, -nqp.y);
                A[q_c*ELD+q_r] = make_float2(nqq.x, -nqq.y);
            }
        } else {
            vt_update(Vt, pq, rnd, tid - 528, csr2[cur], ssr2[cur]);
        }
        __syncthreads();
        // phase2: warp0 -> rotations for r+1; threads 32..559 -> V items 496..1023
        if (tid < 32) {
            if (r + 1 < R) rot_compute(A, pq, nrnd, tid, csr2[nxt], ssr2[nxt]);
        } else if (tid < 560) {
            vt_update(Vt, pq, rnd, 496 + (tid - 32), csr2[cur], ssr2[cur]);
        }
        __syncthreads();
        rnd = nrnd;
    }

    if (tid == 0) {
        float lmax = 0.f;
        for (int i = 0; i < 64; i++) { float l = A[i*ELD+i].x; if (l > lmax) lmax = l; }
        float lamL = lamLp ? fmaxf(lamLp[lamIdx], 0.f) : 0.8f;
        float thr = sqrtf(fmaxf(lmax, 0.f)) * TAU * lamL;
        for (int i = 0; i < 64; i++) {
            float l  = fmaxf(A[i*ELD+i].x, 0.f);
            float sv = sqrtf(l);
            rr[i] = (sv > thr) ? (sv - thr) / sv : 0.f;
        }
    }
    __syncthreads();
    // W[g][f] = sum_i Vt[i][g] * r_i * conj(Vt[i][f])
    {
        int g = tid & 63, f0 = (tid >> 6) << 2;
        float2 w[4];
        #pragma unroll
        for (int j = 0; j < 4; j++) w[j] = make_float2(0.f, 0.f);
        for (int i = 0; i < 64; i++) {
            float2 vg = Vt[i*64 + g];
            float r_ = rr[i];
            float ax = vg.x*r_, ay = vg.y*r_;
            #pragma unroll
            for (int j = 0; j < 4; j++) {
                float2 vf = Vt[i*64 + f0 + j];
                w[j].x += ax*vf.x + ay*vf.y;
                w[j].y += ay*vf.x - ax*vf.y;
            }
        }
        #pragma unroll
        for (int j = 0; j < 4; j++)
            g_W[(g*64 + f0 + j) & 4095] = w[j];
    }
}

// x1new[f][p] = sum_g A1[g][p] * W[g][f]; u1 = 2*x1new - x1old
__global__ __launch_bounds__(256) void k_gemm() {
    __shared__ float2 Ws[64*64];
    __shared__ float2 Asm[8][64];
    int tid = threadIdx.x;
    for (int l = tid; l < 4096; l += 256) Ws[l] = g_W[l & 4095];
    int px0 = (tid & 15) << 2;
    int f0  = (tid >> 4) << 2;
    int p0 = blockIdx.x << 6;
    float2 acc[4][4];
    #pragma unroll
    for (int i = 0; i < 4; i++)
        #pragma unroll
        for (int j = 0; j < 4; j++) acc[i][j] = make_float2(0.f, 0.f);
    __syncthreads();
    for (int g0 = 0; g0 < 64; g0 += 8) {
        for (int l = tid; l < 512; l += 256) {
            int gg = l >> 6, pp = l & 63;
            Asm[gg][pp] = g_A1[IDX((g0+gg)*NPX + p0 + pp)];
        }
        __syncthreads();
        #pragma unroll
        for (int gg = 0; gg < 8; gg++) {
            float4 a01 = *reinterpret_cast<const float4*>(&Asm[gg][px0]);
            float4 a23 = *reinterpret_cast<const float4*>(&Asm[gg][px0+2]);
            float4 w01 = *reinterpret_cast<const float4*>(&Ws[(g0+gg)*64 + f0]);
            float4 w23 = *reinterpret_cast<const float4*>(&Ws[(g0+gg)*64 + f0 + 2]);
            float2 a[4] = { make_float2(a01.x,a01.y), make_float2(a01.z,a01.w),
                            make_float2(a23.x,a23.y), make_float2(a23.z,a23.w) };
            float2 w[4] = { make_float2(w01.x,w01.y), make_float2(w01.z,w01.w),
                            make_float2(w23.x,w23.y), make_float2(w23.z,w23.w) };
            #pragma unroll
            for (int i = 0; i < 4; i++)
                #pragma unroll
                for (int j = 0; j < 4; j++) {
                    acc[i][j].x += a[i].x*w[j].x - a[i].y*w[j].y;
                    acc[i][j].y += a[i].x*w[j].y + a[i].y*w[j].x;
                }
        }
        __syncthreads();
    }
    #pragma unroll
    for (int j = 0; j < 4; j++) {
        #pragma unroll
        for (int i = 0; i < 4; i++) {
            int idx = IDX((f0+j)*NPX + p0 + px0 + i);
            float2 old = g_x1[idx];
            float2 nv  = acc[i][j];
            g_x1[idx] = nv;
            g_u1[idx] = make_float2(2.f*nv.x - old.x, 2.f*nv.y - old.y);
        }
    }
}

// Output writer: buffer is out_size float32 elements; write re(x1+x2).
__global__ __launch_bounds__(256) void k_out(float* __restrict__ out, int nf) {
    for (int i = blockIdx.x*blockDim.x + threadIdx.x; i < nf; i += gridDim.x*blockDim.x) {
        int ii = IDX(i);
        out[i] = g_x1[ii].x + g_x2[ii].x;
    }
}

// ---------------- launch ----------------
extern "C" void kernel_launch(void* const* d_in, const int* in_sizes, int n_in,
                              void* d_out, int out_size) {
    const float* dr = 0; const float* di = 0;
    const float* lamS = 0; const float* lamL = 0;
    int drCap = 0, diCap = 0, lamScnt = 0, lamLcnt = 0;
    for (int i = 0; i < n_in; i++) {
        int sz = in_sizes[i];
        if (sz >= NTOT) {
            if (!dr)      { dr = (const float*)d_in[i]; drCap = sz; }
            else if (!di) { di = (const float*)d_in[i]; diCap = sz; }
        } else if (sz > 0) {
            if (!lamS)      { lamS = (const float*)d_in[i]; lamScnt = sz; }
            else if (!lamL) { lamL = (const float*)d_in[i]; lamLcnt = sz; }
        }
    }
    if (!dr && n_in > 0) { dr = (const float*)d_in[0]; drCap = in_sizes[0]; }
    if (!di && n_in > 1) { di = (const float*)d_in[1]; diCap = in_sizes[1]; }
    int cap = drCap < diCap ? drCap : diCap;
    if (cap > NTOT) cap = NTOT;
    if (cap < 0) cap = 0;

    int nf = out_size;
    if (nf > NTOT) nf = NTOT;
    if (nf < 0) nf = 0;

    // dynamic smem: A + Vt (float2) + pq (ushort2) + tri (uchar2)
    const int eig_smem = (int)((64*ELD + 4096) * sizeof(float2)
                               + 63*32*sizeof(ushort2) + 528*sizeof(uchar2));
    cudaFuncSetAttribute(k_eig, cudaFuncAttributeMaxDynamicSharedMemorySize, eig_smem);

    k_init<<<1, 128>>>();
    k_sumsq<<<256, 256>>>(dr, di, cap);
    k_normred<<<1, 256>>>();
    k_buildD<<<4096, 256>>>(dr, di, cap);

    // startpoint = ifft2(D) -> x1, x2, u1, u2
    k_fft_row<<<2048, 256>>>(0, 1, (const float*)0, 0);
    k_col_start<<<2048, 256>>>();

    for (int it = 0; it < 8; it++) {
        int sIdx = (lamScnt > it) ? it : (lamScnt > 0 ? lamScnt - 1 : 0);
        int lIdx = (lamLcnt > it) ? it : (lamLcnt > 0 ? lamLcnt - 1 : 0);
        k_fft_row<<<2048, 256>>>(1, 0, lamS, sIdx);
        k_col_fused<<<2048, 256>>>();
        k_row_kadj<<<2048, 256>>>();
        k_gram<<<GRAMB, 256>>>();
        k_gramred<<<16, 256>>>();
        k_eig<<<1, 1024, eig_smem>>>(lamL, lIdx);
        k_gemm<<<1024, 256>>>();
    }

    k_out<<<4096, 256>>>((float*)d_out, nf);
}

// round 17
// speedup vs baseline: 1.0197x; 1.0197x over previous
#include <cuda_runtime.h>
#include <math.h>

#define NFR 64
#define NPX 65536          // 256*256
#define NTOT (NFR*NPX)     // 4194304 = 2^22
#define M22  0x3FFFFF      // NTOT-1 safety mask
#define SIGMA 0.35355339059327373f
#define TAU   0.35355339059327373f
#define INV1PS (1.0f/(1.0f+SIGMA))
#define ELD 65             // A smem leading dim (padded)
#define NSWEEP 5
#define GRAMB 128          // gram partial blocks
#define CLD 33             // column-panel smem leading dim (padded, odd)

#define IDX(i) ((i) & M22)

// ---------------- device globals (scratch) ----------------
__device__ float2 g_D[NTOT];
__device__ float2 g_T[NTOT];
__device__ float2 g_y1[NTOT];
__device__ float2 g_y2[NTOT];
__device__ float2 g_x1[NTOT];
__device__ float2 g_x2[NTOT];
__device__ float2 g_u1[NTOT];
__device__ float2 g_u2[NTOT];
__device__ float2 g_A1[NTOT];
__device__ double g_part[256];
__device__ double g_norm2;
__device__ float2 g_Gp[GRAMB][4096];
__device__ float2 g_Gf[4096];
__device__ float2 g_W[4096];
__device__ float2 g_tw[128];

// ---------------- helpers ----------------
__device__ __forceinline__ float2 cadd(float2 a, float2 b){ return make_float2(a.x+b.x, a.y+b.y); }
__device__ __forceinline__ float2 csub(float2 a, float2 b){ return make_float2(a.x-b.x, a.y-b.y); }
__device__ __forceinline__ float2 cmulf(float2 a, float2 b){ return make_float2(a.x*b.x-a.y*b.y, a.x*b.y+a.y*b.x); }
// conj(s)*a
__device__ __forceinline__ float2 cjmul(float2 s, float2 a){ return make_float2(s.x*a.x+s.y*a.y, s.x*a.y-s.y*a.x); }
__device__ __forceinline__ float2 cscale(float2 a, float c){ return make_float2(a.x*c, a.y*c); }

// 256-pt radix-2 DIT FFT on shared memory, one warp per line.
__device__ __forceinline__ void fft256_sm(float2* s, int stride, int lane, int inv) {
    #pragma unroll
    for (int j = 0; j < 8; j++) {
        int i = lane + (j<<5);
        int r = __brev((unsigned)i) >> 24;
        if (r > i) { float2 a = s[i*stride]; s[i*stride] = s[r*stride]; s[r*stride] = a; }
    }
    __syncwarp();
    #pragma unroll
    for (int st = 0; st < 8; st++) {
        int half = 1 << st;
        #pragma unroll
        for (int j = 0; j < 4; j++) {
            int b  = lane + (j<<5);
            int k  = b & (half-1);
            int i0 = ((b >> st) << (st+1)) + k;
            float2 w = g_tw[(k << (7-st)) & 127];
            if (inv) w.y = -w.y;
            float2 u = s[i0*stride];
            float2 v = s[(i0+half)*stride];
            float2 t = cmulf(w, v);
            s[i0*stride]        = cadd(u, t);
            s[(i0+half)*stride] = csub(u, t);
        }
        __syncwarp();
    }
}

// ---------------- init ----------------
__global__ __launch_bounds__(128) void k_init() {
    int t = threadIdx.x & 127;
    double a = -2.0 * 3.14159265358979323846 * (double)t / 256.0;
    g_tw[t] = make_float2((float)cos(a), (float)sin(a));
}

__global__ __launch_bounds__(256) void k_sumsq(const float* __restrict__ dr, const float* __restrict__ di, int cap) {
    double acc = 0.0;
    for (int i = blockIdx.x*blockDim.x + threadIdx.x; i < cap; i += gridDim.x*blockDim.x) {
        float a = dr[i], b = di[i];
        acc += (double)a*(double)a + (double)b*(double)b;
    }
    __shared__ double ws[256];
    ws[threadIdx.x] = acc;
    __syncthreads();
    for (int o = 128; o; o >>= 1) {
        if (threadIdx.x < o) ws[threadIdx.x] += ws[threadIdx.x + o];
        __syncthreads();
    }
    if (threadIdx.x == 0) g_part[blockIdx.x & 255] = ws[0];
}

__global__ __launch_bounds__(256) void k_normred() {
    __shared__ double ws[256];
    ws[threadIdx.x] = g_part[threadIdx.x & 255];
    __syncthreads();
    for (int o = 128; o; o >>= 1) {
        if (threadIdx.x < o) ws[threadIdx.x] += ws[threadIdx.x + o];
        __syncthreads();
    }
    if (threadIdx.x == 0) g_norm2 = ws[0];
}

__global__ __launch_bounds__(256) void k_buildD(const float* __restrict__ dr, const float* __restrict__ di, int cap) {
    float inv = (float)(1.0 / sqrt(g_norm2));
    for (int i = blockIdx.x*blockDim.x + threadIdx.x; i < NTOT; i += gridDim.x*blockDim.x) {
        float a = (i < cap) ? dr[i] : 0.f;
        float b = (i < cap) ? di[i] : 0.f;
        g_D[IDX(i)]  = make_float2(a*inv, b*inv);
        g_y1[IDX(i)] = make_float2(0.f, 0.f);
        g_y2[IDX(i)] = make_float2(0.f, 0.f);
    }
}

// ---------------- FFT row pass ----------------
__global__ __launch_bounds__(256) void k_fft_row(int mode, int inv, const float* __restrict__ lamSp, int lamIdx) {
    __shared__ float2 sm[8*256];
    int warp = threadIdx.x >> 5, lane = threadIdx.x & 31;
    int line = (blockIdx.x << 3) + warp;
    int base = line << 8;
    int f = line >> 8;
    float2* s = sm + (warp << 8);
    if (mode == 1) {
        float lamS = lamSp ? fmaxf(lamSp[lamIdx], 0.f) : 0.01f;
        float l2 = lamS*lamS;
        #pragma unroll
        for (int j = 0; j < 8; j++) {
            int i = lane + (j<<5);
            float2 u1v = g_u1[IDX(base+i)];
            float2 u2v = g_u2[IDX(base+i)];
            s[i] = cadd(u1v, u2v);
            float2 a = g_y2[IDX(base+i)];
            if (f < NFR-1) {
                float2 un = g_u2[IDX(base+i+NPX)];
                a.x += SIGMA*(un.x - u2v.x);
                a.y += SIGMA*(un.y - u2v.y);
            }
            float m2 = a.x*a.x + a.y*a.y;
            if (m2 > l2) {
                float sc = lamS * rsqrtf(m2);
                a.x *= sc; a.y *= sc;
            }
            g_y2[IDX(base+i)] = a;
        }
    } else {
        #pragma unroll
        for (int j = 0; j < 8; j++) { int i = lane + (j<<5); s[i] = g_D[IDX(base+i)]; }
    }
    __syncwarp();
    fft256_sm(s, 1, lane, inv);
    #pragma unroll
    for (int j = 0; j < 8; j++) {
        int i = lane + (j<<5);
        float2 v = s[i];
        g_T[IDX(base+i)] = make_float2(v.x*0.0625f, v.y*0.0625f);
    }
}

// startpoint: wide inverse col pass (32 cols/block, coalesced); broadcast to x1,x2,u1,u2
__global__ __launch_bounds__(1024) void k_col_start() {
    extern __shared__ float2 smw[];        // 256*CLD
    int f = blockIdx.x >> 3, x0 = (blockIdx.x & 7) << 5;
    int fb = f << 16;
    int w = threadIdx.x >> 5, lane = threadIdx.x & 31;
    #pragma unroll
    for (int j = 0; j < 8; j++) {
        int y = (j<<5) + w;
        smw[y*CLD + lane] = g_T[IDX(fb + (y<<8) + x0 + lane)];
    }
    __syncthreads();
    fft256_sm(smw + w, CLD, lane, 1);      // warp w handles column w
    __syncthreads();
    #pragma unroll
    for (int j = 0; j < 8; j++) {
        int y = (j<<5) + w;
        int idx = IDX(fb + (y<<8) + x0 + lane);
        float2 v = smw[y*CLD + lane];
        v = make_float2(v.x*0.0625f, v.y*0.0625f);
        g_x1[idx] = v; g_x2[idx] = v; g_u1[idx] = v; g_u2[idx] = v;
    }
}

// FUSED wide column pass: forward col FFT -> y1 dual update -> inverse col FFT.
__global__ __launch_bounds__(1024) void k_col_fused() {
    extern __shared__ float2 smw[];        // 256*CLD
    int f = blockIdx.x >> 3, x0 = (blockIdx.x & 7) << 5;
    int fb = f << 16;
    int w = threadIdx.x >> 5, lane = threadIdx.x & 31;
    #pragma unroll
    for (int j = 0; j < 8; j++) {
        int y = (j<<5) + w;
        smw[y*CLD + lane] = g_T[IDX(fb + (y<<8) + x0 + lane)];
    }
    __syncthreads();
    fft256_sm(smw + w, CLD, lane, 0);      // forward column FFT
    __syncthreads();
    // y1' = (y1 + sigma*(Ku1 - D)) / (1+sigma); coalesced elementwise
    #pragma unroll
    for (int j = 0; j < 8; j++) {
        int y = (j<<5) + w;
        int idx = IDX(fb + (y<<8) + x0 + lane);
        float2 v = smw[y*CLD + lane];
        v.x *= 0.0625f; v.y *= 0.0625f;    // true Ku1
        float2 d = g_D[idx];
        float2 yv = g_y1[idx];
        yv.x = (yv.x + SIGMA*(v.x - d.x)) * INV1PS;
        yv.y = (yv.y + SIGMA*(v.y - d.y)) * INV1PS;
        g_y1[idx] = yv;
        smw[y*CLD + lane] = yv;
    }
    __syncthreads();
    fft256_sm(smw + w, CLD, lane, 1);      // inverse column FFT of y1'
    __syncthreads();
    #pragma unroll
    for (int j = 0; j < 8; j++) {
        int y = (j<<5) + w;
        float2 v = smw[y*CLD + lane];
        g_T[IDX(fb + (y<<8) + x0 + lane)] = make_float2(v.x*0.0625f, v.y*0.0625f);
    }
}

// inverse ROW pass of g_T -> Kadjy1; fused argg1 and x2/u2 updates
__global__ __launch_bounds__(256) void k_row_kadj() {
    __shared__ float2 smr[8*256];
    int warp = threadIdx.x >> 5, lane = threadIdx.x & 31;
    int line = (blockIdx.x << 3) + warp;
    int base = line << 8;
    int f = line >> 8;
    float2* s = smr + (warp << 8);
    #pragma unroll
    for (int j = 0; j < 8; j++) { int i = lane + (j<<5); s[i] = g_T[IDX(base+i)]; }
    __syncwarp();
    fft256_sm(s, 1, lane, 1);
    #pragma unroll
    for (int j = 0; j < 8; j++) {
        int i = lane + (j<<5);
        int idx = IDX(base + i);
        float2 v = s[i];
        v.x *= 0.0625f; v.y *= 0.0625f;   // Kadjy1
        float2 x = g_x1[idx];
        g_A1[idx] = make_float2(x.x - TAU*v.x, x.y - TAU*v.y);
        float2 kadj;
        if (f == 0) {
            float2 yc = g_y2[idx];
            kadj = make_float2(v.x - yc.x, v.y - yc.y);
        } else if (f == NFR-1) {
            float2 ym = g_y2[IDX(idx - NPX)];
            kadj = make_float2(v.x + ym.x, v.y + ym.y);
        } else {
            float2 yc = g_y2[idx];
            float2 ym = g_y2[IDX(idx - NPX)];
            kadj = make_float2(v.x - (yc.x - ym.x), v.y - (yc.y - ym.y));
        }
        float2 xo = g_x2[idx];
        float2 xn = make_float2(xo.x - TAU*kadj.x, xo.y - TAU*kadj.y);
        g_x2[idx] = xn;
        g_u2[idx] = make_float2(2.f*xn.x - xo.x, 2.f*xn.y - xo.y);
    }
}

// Gram partials with 4x4 register blocking.
__global__ __launch_bounds__(256) void k_gram() {
    __shared__ float2 tile[64][33];
    int tid = threadIdx.x;
    int tx = tid & 15, ty = tid >> 4;
    float2 acc[4][4];
    #pragma unroll
    for (int i = 0; i < 4; i++)
        #pragma unroll
        for (int j = 0; j < 4; j++) acc[i][j] = make_float2(0.f, 0.f);
    int p0 = blockIdx.x * (NPX / GRAMB);
    for (int pt = 0; pt < NPX/GRAMB; pt += 32) {
        for (int l = tid; l < 2048; l += 256) {
            int gg = l >> 5, pp = l & 31;
            tile[gg][pp] = g_A1[IDX(gg*NPX + p0 + pt + pp)];
        }
        __syncthreads();
        for (int p = 0; p < 32; p++) {
            float2 ag[4], bh[4];
            #pragma unroll
            for (int i = 0; i < 4; i++) ag[i] = tile[ty + 16*i][p];
            #pragma unroll
            for (int j = 0; j < 4; j++) bh[j] = tile[tx + 16*j][p];
            #pragma unroll
            for (int i = 0; i < 4; i++)
                #pragma unroll
                for (int j = 0; j < 4; j++) {
                    float2 a = ag[i], b = bh[j];
                    acc[i][j].x += a.x*b.x + a.y*b.y;   // conj(a)*b
                    acc[i][j].y += a.x*b.y - a.y*b.x;
                }
        }
        __syncthreads();
    }
    #pragma unroll
    for (int i = 0; i < 4; i++)
        #pragma unroll
        for (int j = 0; j < 4; j++)
            g_Gp[blockIdx.x & (GRAMB-1)][((ty+16*i)*64 + tx+16*j) & 4095] = acc[i][j];
}

__global__ __launch_bounds__(256) void k_gramred() {
    int idx = (blockIdx.x*blockDim.x + threadIdx.x) & 4095;
    double sx = 0.0, sy = 0.0;
    for (int b = 0; b < GRAMB; b++) {
        float2 v = g_Gp[b][idx];
        sx += (double)v.x; sy += (double)v.y;
    }
    g_Gf[idx] = make_float2((float)sx, (float)sy);
}

// rotation computation for pair k of round rnd (reads A only)
__device__ __forceinline__ void rot_compute(const float2* A, const ushort2* pq,
                                            int rnd, int k, float* csr, float2* ssr) {
    ushort2 e = pq[rnd*32 + k];
    int p = e.x, q = e.y;
    float app = A[p*ELD+p].x, aqq = A[q*ELD+q].x;
    float2 apq = A[p*ELD+q];
    float ab = sqrtf(apq.x*apq.x + apq.y*apq.y);
    float c = 1.f; float2 s = make_float2(0.f, 0.f);
    if (ab > 1e-30f) {
        float tt = (aqq - app) / (2.f*ab);
        float t  = 1.f / (fabsf(tt) + sqrtf(1.f + tt*tt));
        if (tt < 0.f) t = -t;
        c = rsqrtf(1.f + t*t);
        float sg = t * c;
        s = make_float2(apq.x/ab*sg, apq.y/ab*sg);
    }
    csr[k] = c; ssr[k] = s;
}

// ---- 64x64 Hermitian eigensolver: software-pipelined parallel Jacobi (R14) ----
// 1024 threads. Per round: phase1 = A update (all warps);
// phase2 = warp0 computes next round's rotations WHILE warps 1-31 update V.
__global__ __launch_bounds__(1024) void k_eig(const float* __restrict__ lamLp, int lamIdx) {
    extern __shared__ float2 es[];
    float2*  A  = es;                        // 64*ELD
    float2*  Vt = es + 64*ELD;               // 4096: Vt[i*64+r] = V[r][i]
    ushort2* pq = (ushort2*)(es + 64*ELD + 4096);  // 63*32
    __shared__ float  csr2[2][32];
    __shared__ float2 ssr2[2][32];
    __shared__ float  rr[64];
    int tid = threadIdx.x;   // 1024 threads

    for (int l = tid; l < 4096; l += 1024) {
        int r = l >> 6, c = l & 63;
        A[r*ELD + c] = g_Gf[l & 4095];
        Vt[l & 4095] = (r == c) ? make_float2(1.f, 0.f) : make_float2(0.f, 0.f);
    }
    for (int l = tid; l < 63*32; l += 1024) {
        int rnd = l >> 5, k = l & 31;
        int p, q;
        if (k == 0) { p = 63; q = rnd; }
        else { p = (rnd + k) % 63; q = (rnd - k + 63) % 63; }
        pq[l] = make_ushort2((unsigned short)p, (unsigned short)q);
    }
    __syncthreads();

    if (tid < 32) rot_compute(A, pq, 0, tid, csr2[0], ssr2[0]);
    __syncthreads();

    const int R = NSWEEP*63;
    int rnd = 0;
    for (int r = 0; r < R; r++) {
        int cur = r & 1, nxt = cur ^ 1;
        int nrnd = (rnd + 1 == 63) ? 0 : rnd + 1;
        // phase1: A update, one disjoint 2x2 block per thread
        {
            int kr = tid >> 5, kc = tid & 31;
            ushort2 er = pq[rnd*32 + kr], ec = pq[rnd*32 + kc];
            int p_r = er.x, q_r = er.y, p_c = ec.x, q_c = ec.y;
            float cc = csr2[cur][kc]; float2 sc = ssr2[cur][kc];
            float cr = csr2[cur][kr]; float2 sr = ssr2[cur][kr];
            float2 app = A[p_r*ELD+p_c], apq = A[p_r*ELD+q_c];
            float2 aqp = A[q_r*ELD+p_c], aqq = A[q_r*ELD+q_c];
            float2 bpp = csub(cscale(app, cc), cjmul(sc, apq));
            float2 bpq = cadd(cmulf(sc, app), cscale(apq, cc));
            float2 bqp = csub(cscale(aqp, cc), cjmul(sc, aqq));
            float2 bqq = cadd(cmulf(sc, aqp), cscale(aqq, cc));
            A[p_r*ELD+p_c] = csub(cscale(bpp, cr), cmulf(sr, bqp));
            A[p_r*ELD+q_c] = csub(cscale(bpq, cr), cmulf(sr, bqq));
            A[q_r*ELD+p_c] = cadd(cjmul(sr, bpp), cscale(bqp, cr));
            A[q_r*ELD+q_c] = cadd(cjmul(sr, bpq), cscale(bqq, cr));
        }
        __syncthreads();
        // phase2: warp0 -> rotations for r+1; warps 1..31 -> V update for r
        if (tid < 32) {
            if (r + 1 < R) rot_compute(A, pq, nrnd, tid, csr2[nxt], ssr2[nxt]);
        } else {
            int u = tid - 32;
            #pragma unroll
            for (int pass = 0; pass < 2; pass++) {
                int uu = (pass == 0) ? u : u + 992;
                if (pass == 1 && u >= 32) break;
                int k = uu >> 5, ch = uu & 31;
                ushort2 e = pq[rnd*32 + k];
                int p = e.x, q = e.y;
                float c = csr2[cur][k]; float2 s = ssr2[cur][k];
                int r2 = ch << 1;
                float4* vp4 = reinterpret_cast<float4*>(&Vt[p*64 + r2]);
                float4* vq4 = reinterpret_cast<float4*>(&Vt[q*64 + r2]);
                float4 vp = *vp4, vq = *vq4;
                float2 vp0 = make_float2(vp.x, vp.y), vp1 = make_float2(vp.z, vp.w);
                float2 vq0 = make_float2(vq.x, vq.y), vq1 = make_float2(vq.z, vq.w);
                float2 np0 = csub(cscale(vp0, c), cjmul(s, vq0));
                float2 nq0 = cadd(cmulf(s, vp0), cscale(vq0, c));
                float2 np1 = csub(cscale(vp1, c), cjmul(s, vq1));
                float2 nq1 = cadd(cmulf(s, vp1), cscale(vq1, c));
                *vp4 = make_float4(np0.x, np0.y, np1.x, np1.y);
                *vq4 = make_float4(nq0.x, nq0.y, nq1.x, nq1.y);
            }
        }
        __syncthreads();
        rnd = nrnd;
    }

    if (tid == 0) {
        float lmax = 0.f;
        for (int i = 0; i < 64; i++) { float l = A[i*ELD+i].x; if (l > lmax) lmax = l; }
        float lamL = lamLp ? fmaxf(lamLp[lamIdx], 0.f) : 0.8f;
        float thr = sqrtf(fmaxf(lmax, 0.f)) * TAU * lamL;
        for (int i = 0; i < 64; i++) {
            float l  = fmaxf(A[i*ELD+i].x, 0.f);
            float sv = sqrtf(l);
            rr[i] = (sv > thr) ? (sv - thr) / sv : 0.f;
        }
    }
    __syncthreads();
    // W[g][f] = sum_i Vt[i][g] * r_i * conj(Vt[i][f])
    {
        int g = tid & 63, f0 = (tid >> 6) << 2;
        float2 w[4];
        #pragma unroll
        for (int j = 0; j < 4; j++) w[j] = make_float2(0.f, 0.f);
        for (int i = 0; i < 64; i++) {
            float2 vg = Vt[i*64 + g];
            float r_ = rr[i];
            float ax = vg.x*r_, ay = vg.y*r_;
            #pragma unroll
            for (int j = 0; j < 4; j++) {
                float2 vf = Vt[i*64 + f0 + j];
                w[j].x += ax*vf.x + ay*vf.y;
                w[j].y += ay*vf.x - ax*vf.y;
            }
        }
        #pragma unroll
        for (int j = 0; j < 4; j++)
            g_W[(g*64 + f0 + j) & 4095] = w[j];
    }
}

// x1new[f][p] = sum_g A1[g][p] * W[g][f]; u1 = 2*x1new - x1old
__global__ __launch_bounds__(256) void k_gemm() {
    __shared__ float2 Ws[64*64];
    __shared__ float2 Asm[8][64];
    int tid = threadIdx.x;
    for (int l = tid; l < 4096; l += 256) Ws[l] = g_W[l & 4095];
    int px0 = (tid & 15) << 2;
    int f0  = (tid >> 4) << 2;
    int p0 = blockIdx.x << 6;
    float2 acc[4][4];
    #pragma unroll
    for (int i = 0; i < 4; i++)
        #pragma unroll
        for (int j = 0; j < 4; j++) acc[i][j] = make_float2(0.f, 0.f);
    __syncthreads();
    for (int g0 = 0; g0 < 64; g0 += 8) {
        for (int l = tid; l < 512; l += 256) {
            int gg = l >> 6, pp = l & 63;
            Asm[gg][pp] = g_A1[IDX((g0+gg)*NPX + p0 + pp)];
        }
        __syncthreads();
        #pragma unroll
        for (int gg = 0; gg < 8; gg++) {
            float4 a01 = *reinterpret_cast<const float4*>(&Asm[gg][px0]);
            float4 a23 = *reinterpret_cast<const float4*>(&Asm[gg][px0+2]);
            float4 w01 = *reinterpret_cast<const float4*>(&Ws[(g0+gg)*64 + f0]);
            float4 w23 = *reinterpret_cast<const float4*>(&Ws[(g0+gg)*64 + f0 + 2]);
            float2 a[4] = { make_float2(a01.x,a01.y), make_float2(a01.z,a01.w),
                            make_float2(a23.x,a23.y), make_float2(a23.z,a23.w) };
            float2 w[4] = { make_float2(w01.x,w01.y), make_float2(w01.z,w01.w),
                            make_float2(w23.x,w23.y), make_float2(w23.z,w23.w) };
            #pragma unroll
            for (int i = 0; i < 4; i++)
                #pragma unroll
                for (int j = 0; j < 4; j++) {
                    acc[i][j].x += a[i].x*w[j].x - a[i].y*w[j].y;
                    acc[i][j].y += a[i].x*w[j].y + a[i].y*w[j].x;
                }
        }
        __syncthreads();
    }
    #pragma unroll
    for (int j = 0; j < 4; j++) {
        #pragma unroll
        for (int i = 0; i < 4; i++) {
            int idx = IDX((f0+j)*NPX + p0 + px0 + i);
            float2 old = g_x1[idx];
            float2 nv  = acc[i][j];
            g_x1[idx] = nv;
            g_u1[idx] = make_float2(2.f*nv.x - old.x, 2.f*nv.y - old.y);
        }
    }
}

// Output writer: buffer is out_size float32 elements; write re(x1+x2).
__global__ __launch_bounds__(256) void k_out(float* __restrict__ out, int nf) {
    for (int i = blockIdx.x*blockDim.x + threadIdx.x; i < nf; i += gridDim.x*blockDim.x) {
        int ii = IDX(i);
        out[i] = g_x1[ii].x + g_x2[ii].x;
    }
}

// ---------------- launch ----------------
extern "C" void kernel_launch(void* const* d_in, const int* in_sizes, int n_in,
                              void* d_out, int out_size) {
    const float* dr = 0; const float* di = 0;
    const float* lamS = 0; const float* lamL = 0;
    int drCap = 0, diCap = 0, lamScnt = 0, lamLcnt = 0;
    for (int i = 0; i < n_in; i++) {
        int sz = in_sizes[i];
        if (sz >= NTOT) {
            if (!dr)      { dr = (const float*)d_in[i]; drCap = sz; }
            else if (!di) { di = (const float*)d_in[i]; diCap = sz; }
        } else if (sz > 0) {
            if (!lamS)      { lamS = (const float*)d_in[i]; lamScnt = sz; }
            else if (!lamL) { lamL = (const float*)d_in[i]; lamLcnt = sz; }
        }
    }
    if (!dr && n_in > 0) { dr = (const float*)d_in[0]; drCap = in_sizes[0]; }
    if (!di && n_in > 1) { di = (const float*)d_in[1]; diCap = in_sizes[1]; }
    int cap = drCap < diCap ? drCap : diCap;
    if (cap > NTOT) cap = NTOT;
    if (cap < 0) cap = 0;

    int nf = out_size;
    if (nf > NTOT) nf = NTOT;
    if (nf < 0) nf = 0;

    const int eig_smem = (int)((64*ELD + 4096) * sizeof(float2) + 63*32*sizeof(ushort2));
    const int col_smem = (int)(256*CLD*sizeof(float2));   // 67,584 B
    cudaFuncSetAttribute(k_eig, cudaFuncAttributeMaxDynamicSharedMemorySize, eig_smem);
    cudaFuncSetAttribute(k_col_start, cudaFuncAttributeMaxDynamicSharedMemorySize, col_smem);
    cudaFuncSetAttribute(k_col_fused, cudaFuncAttributeMaxDynamicSharedMemorySize, col_smem);

    k_init<<<1, 128>>>();
    k_sumsq<<<256, 256>>>(dr, di, cap);
    k_normred<<<1, 256>>>();
    k_buildD<<<4096, 256>>>(dr, di, cap);

    // startpoint = ifft2(D) -> x1, x2, u1, u2
    k_fft_row<<<2048, 256>>>(0, 1, (const float*)0, 0);
    k_col_start<<<512, 1024, col_smem>>>();

    for (int it = 0; it < 8; it++) {
        int sIdx = (lamScnt > it) ? it : (lamScnt > 0 ? lamScnt - 1 : 0);
        int lIdx = (lamLcnt > it) ? it : (lamLcnt > 0 ? lamLcnt - 1 : 0);
        k_fft_row<<<2048, 256>>>(1, 0, lamS, sIdx);
        k_col_fused<<<512, 1024, col_smem>>>();
        k_row_kadj<<<2048, 256>>>();
        k_gram<<<GRAMB, 256>>>();
        k_gramred<<<16, 256>>>();
        k_eig<<<1, 1024, eig_smem>>>(lamL, lIdx);
        k_gemm<<<1024, 256>>>();
    }

    k_out<<<4096, 256>>>((float*)d_out, nf);
}